// round 1
// baseline (speedup 1.0000x reference)
#include <cuda_runtime.h>

// SimpleSNN: T=500 sequential steps, B=2048 batch, 12 -> 38 (RLeaky) -> 7 (Leaky)
// Outputs (concatenated flat): spk1[T,B,38], mem1[T,B,38], spk2[T,B,7], mem2[T,B,7]

#define T_STEPS 500
#define BATCH   2048
#define NIN     12
#define NL1     38
#define NL2     7
#define NB      4              // batch elements per block
#define NTHREADS 192
#define L1_THREADS (NB*NL1)    // 152
#define L2_BASE    160         // layer-2 threads start at a warp boundary
#define L2_THREADS (NB*NL2)    // 28
#define X_THREADS  (NB*NIN)    // 48

__global__ __launch_bounds__(NTHREADS, 1)
void snn_scan_kernel(const float* __restrict__ x,
                     const float* __restrict__ W1,
                     const float* __restrict__ V,
                     const float* __restrict__ W2,
                     const float* __restrict__ pb1,
                     const float* __restrict__ pb2,
                     const float* __restrict__ pth,
                     float* __restrict__ out)
{
    __shared__ float xsh[X_THREADS];     // x tile for this step: NB*12 floats
    __shared__ float s1sh[NB * 40];      // spk1 staging, padded to 40/batch for float4 loads

    const int tid = threadIdx.x;
    const int b0  = blockIdx.x * NB;

    const float beta1 = *pb1;
    const float beta2 = *pb2;
    const float thr   = *pth;

    float* __restrict__ outSpk1 = out;
    float* __restrict__ outMem1 = out + (size_t)T_STEPS * BATCH * NL1;
    float* __restrict__ outSpk2 = out + (size_t)2 * T_STEPS * BATCH * NL1;
    float* __restrict__ outMem2 = out + (size_t)2 * T_STEPS * BATCH * NL1
                                      + (size_t)T_STEPS * BATCH * NL2;

    const bool isX  = (tid < X_THREADS);
    const bool isL1 = (tid < L1_THREADS);
    const bool isL2 = (tid >= L2_BASE) && (tid < L2_BASE + L2_THREADS);

    // ---- layer 1 thread state ----
    float w1r[NIN];
    float vj = 0.0f, mem1 = 0.0f, spk1 = 0.0f;
    size_t o1 = 0;
    int s1idx = 0, xoff = 0;
    if (isL1) {
        int bl = tid / NL1;
        int j  = tid - bl * NL1;
        #pragma unroll
        for (int i = 0; i < NIN; ++i) w1r[i] = W1[j * NIN + i];
        vj    = V[j];
        o1    = (size_t)(b0 + bl) * NL1 + j;
        s1idx = bl * 40 + j;
        xoff  = bl * NIN;
    }

    // ---- layer 2 thread state ----
    float w2r[40];
    float mem2 = 0.0f;
    size_t o2 = 0;
    int s2off = 0;
    if (isL2) {
        int t2 = tid - L2_BASE;
        int bl = t2 / NL2;
        int k  = t2 - bl * NL2;
        #pragma unroll
        for (int j = 0; j < NL1; ++j) w2r[j] = W2[k * NL1 + j];
        w2r[38] = 0.0f; w2r[39] = 0.0f;
        o2    = (size_t)(b0 + bl) * NL2 + k;
        s2off = bl * 40;
    }

    // zero the shared padding lanes once (never rewritten)
    if (tid < NB) {
        s1sh[tid * 40 + 38] = 0.0f;
        s1sh[tid * 40 + 39] = 0.0f;
    }

    // prefetch x[t=0] into registers
    const size_t stepx = (size_t)BATCH * NIN;
    const size_t step1 = (size_t)BATCH * NL1;
    const size_t step2 = (size_t)BATCH * NL2;
    size_t xbase = (size_t)b0 * NIN + tid;   // valid for tid < 48: == (b0+bl)*12 + i
    float xn = 0.0f;
    if (isX) xn = x[xbase];

    __syncthreads();

    #pragma unroll 1
    for (int t = 0; t < T_STEPS; ++t) {
        // stage this step's x tile into shared
        if (isX) xsh[tid] = xn;
        __syncthreads();   // A: xsh ready; also fences last step's layer-2 reads of s1sh

        // prefetch next step's x (latency hidden behind this step's compute)
        if (isX && (t + 1 < T_STEPS)) xn = x[xbase + (size_t)(t + 1) * stepx];

        if (isL1) {
            const float4* xv = reinterpret_cast<const float4*>(&xsh[xoff]);
            float4 a = xv[0], b = xv[1], c = xv[2];
            float cur = a.x * w1r[0];
            cur = fmaf(a.y, w1r[1], cur);
            cur = fmaf(a.z, w1r[2], cur);
            cur = fmaf(a.w, w1r[3], cur);
            cur = fmaf(b.x, w1r[4], cur);
            cur = fmaf(b.y, w1r[5], cur);
            cur = fmaf(b.z, w1r[6], cur);
            cur = fmaf(b.w, w1r[7], cur);
            cur = fmaf(c.x, w1r[8], cur);
            cur = fmaf(c.y, w1r[9], cur);
            cur = fmaf(c.z, w1r[10], cur);
            cur = fmaf(c.w, w1r[11], cur);

            // mem1 = beta1*mem1 + cur1 + V*spk1_prev
            float m = fmaf(beta1, mem1, cur);
            m = fmaf(vj, spk1, m);
            float s = (m - thr) > 0.0f ? 1.0f : 0.0f;
            m = fmaf(-s, thr, m);            // subtract reset
            mem1 = m;
            spk1 = s;

            s1sh[s1idx] = s;
            size_t oo = (size_t)t * step1 + o1;
            outSpk1[oo] = s;
            outMem1[oo] = m;
        }
        __syncthreads();   // B: s1sh ready for layer 2

        if (isL2) {
            const float4* sv = reinterpret_cast<const float4*>(&s1sh[s2off]);
            float acc0 = 0.0f, acc1 = 0.0f, acc2 = 0.0f, acc3 = 0.0f;
            #pragma unroll
            for (int q = 0; q < 10; ++q) {
                float4 s4 = sv[q];
                acc0 = fmaf(s4.x, w2r[4 * q + 0], acc0);
                acc1 = fmaf(s4.y, w2r[4 * q + 1], acc1);
                acc2 = fmaf(s4.z, w2r[4 * q + 2], acc2);
                acc3 = fmaf(s4.w, w2r[4 * q + 3], acc3);
            }
            float cur2 = (acc0 + acc1) + (acc2 + acc3);
            float m = fmaf(beta2, mem2, cur2);
            float s = (m - thr) > 0.0f ? 1.0f : 0.0f;
            m = fmaf(-s, thr, m);
            mem2 = m;

            size_t oo = (size_t)t * step2 + o2;
            outSpk2[oo] = s;
            outMem2[oo] = m;
        }
    }
}

extern "C" void kernel_launch(void* const* d_in, const int* in_sizes, int n_in,
                              void* d_out, int out_size)
{
    const float* x   = (const float*)d_in[0];
    const float* W1  = (const float*)d_in[1];
    const float* V   = (const float*)d_in[2];
    const float* W2  = (const float*)d_in[3];
    const float* b1  = (const float*)d_in[4];
    const float* b2  = (const float*)d_in[5];
    const float* th  = (const float*)d_in[6];
    float* out = (float*)d_out;

    dim3 grid(BATCH / NB);   // 512 blocks, all resident in one wave
    dim3 block(NTHREADS);
    snn_scan_kernel<<<grid, block>>>(x, W1, V, W2, b1, b2, th, out);
}

// round 2
// speedup vs baseline: 1.6854x; 1.6854x over previous
#include <cuda_runtime.h>

// SimpleSNN: T=500 sequential steps, B=2048, 12 -> 38 (RLeaky) -> 7 (Leaky)
// Outputs flat: spk1[T,B,38], mem1[T,B,38], spk2[T,B,7], mem2[T,B,7]

#define T_STEPS  500
#define BATCH    2048
#define NIN      12
#define NL1      38
#define NL2      7
#define NB       4              // batch elements per block
#define NTHREADS 192
#define L1_THREADS (NB*NL1)     // 152
#define L2_BASE    160          // layer-2 threads start at a warp boundary
#define L2_THREADS (NB*NL2)     // 28
#define X_THREADS  (NB*NIN)     // 48
#define W2STRIDE   44           // pad W2 rows: 44*4B=176B -> distinct bank groups per k

__global__ __launch_bounds__(NTHREADS, 4)
void snn_scan_kernel(const float* __restrict__ x,
                     const float* __restrict__ W1,
                     const float* __restrict__ V,
                     const float* __restrict__ W2,
                     const float* __restrict__ pb1,
                     const float* __restrict__ pb2,
                     const float* __restrict__ pth,
                     float* __restrict__ out)
{
    __shared__ float xsh[2][X_THREADS];     // double-buffered x tile
    __shared__ float s1sh[2][NB * 40];      // double-buffered spk1 staging (pad 40)
    __shared__ float w2sh[NL2 * W2STRIDE];  // W2 rows, padded stride

    const int tid = threadIdx.x;
    const int b0  = blockIdx.x * NB;

    const float beta1 = *pb1;
    const float beta2 = *pb2;
    const float thr   = *pth;

    // ---- one-time shared init ----
    for (int i = tid; i < NL2 * W2STRIDE; i += NTHREADS) {
        int k = i / W2STRIDE;
        int j = i - k * W2STRIDE;
        w2sh[i] = (j < NL1) ? W2[k * NL1 + j] : 0.0f;
    }
    if (tid < 16) {  // zero the padding lanes of both s1 buffers
        int p = tid >> 3, b = (tid >> 1) & 3, c = tid & 1;
        s1sh[p][b * 40 + 38 + c] = 0.0f;
    }

    const bool isX  = (tid < X_THREADS);
    const bool isL1 = (tid < L1_THREADS);
    const bool isL2 = (tid >= L2_BASE) && (tid < L2_BASE + L2_THREADS);

    // ---- layer 1 per-thread state ----
    float w1r[NIN];
    float vj = 0.0f, mem1 = 0.0f, spk1 = 0.0f;
    int s1idx = 0, xoff = 0;
    float *pS1 = out, *pM1 = out;
    if (isL1) {
        int bl = tid / NL1;
        int j  = tid - bl * NL1;
        #pragma unroll
        for (int i = 0; i < NIN; ++i) w1r[i] = W1[j * NIN + i];
        vj    = V[j];
        s1idx = bl * 40 + j;
        xoff  = bl * NIN;
        size_t o = (size_t)(b0 + bl) * NL1 + j;
        pS1 = out + o;
        pM1 = out + (size_t)T_STEPS * BATCH * NL1 + o;
    }

    // ---- layer 2 per-thread state (weights live in shared) ----
    float mem2 = 0.0f;
    int s2off = 0;
    const float4* w2v = (const float4*)w2sh;
    float *pS2 = out, *pM2 = out;
    if (isL2) {
        int t2 = tid - L2_BASE;
        int bl = t2 / NL2;
        int k  = t2 - bl * NL2;
        s2off = bl * 40;
        w2v   = (const float4*)&w2sh[k * W2STRIDE];
        size_t o = (size_t)(b0 + bl) * NL2 + k;
        pS2 = out + (size_t)2 * T_STEPS * BATCH * NL1 + o;
        pM2 = out + (size_t)2 * T_STEPS * BATCH * NL1
                  + (size_t)T_STEPS * BATCH * NL2 + o;
    }

    // ---- x prefetch pipeline: stage t=0 into xsh[0], hold t=1 in xn ----
    const size_t stepx = (size_t)BATCH * NIN;
    const size_t step1 = (size_t)BATCH * NL1;
    const size_t step2 = (size_t)BATCH * NL2;
    const float* xp = x + (size_t)b0 * NIN + tid;  // valid layout for tid < 48
    float xn = 0.0f;
    if (isX) {
        xsh[0][tid] = xp[0];
        xn = xp[stepx];
        xp += 2 * stepx;
    }
    __syncthreads();

    // One barrier per step. Iteration t:
    //   pre-BAR : L1 reads xsh[P], writes s1sh[P] + STG; X stages xsh[P^1] for t+1
    //   BAR
    //   post-BAR: L2 reads s1sh[P] + STG
    // All buffer reuse pairs are separated by exactly one barrier.
#define SNN_STEP(P, TCUR)                                                     \
    {                                                                          \
        if (isL1) {                                                            \
            const float4* xv = reinterpret_cast<const float4*>(&xsh[P][xoff]); \
            float4 a = xv[0], b = xv[1], c = xv[2];                            \
            float cur = a.x * w1r[0];                                          \
            cur = fmaf(a.y, w1r[1], cur);                                      \
            cur = fmaf(a.z, w1r[2], cur);                                      \
            cur = fmaf(a.w, w1r[3], cur);                                      \
            cur = fmaf(b.x, w1r[4], cur);                                      \
            cur = fmaf(b.y, w1r[5], cur);                                      \
            cur = fmaf(b.z, w1r[6], cur);                                      \
            cur = fmaf(b.w, w1r[7], cur);                                      \
            cur = fmaf(c.x, w1r[8], cur);                                      \
            cur = fmaf(c.y, w1r[9], cur);                                      \
            cur = fmaf(c.z, w1r[10], cur);                                     \
            cur = fmaf(c.w, w1r[11], cur);                                     \
            float m = fmaf(beta1, mem1, cur);                                  \
            m = fmaf(vj, spk1, m);                                             \
            float s = (m > thr) ? 1.0f : 0.0f;                                 \
            m = fmaf(-s, thr, m);                                              \
            mem1 = m; spk1 = s;                                                \
            s1sh[P][s1idx] = s;                                                \
            *pS1 = s; *pM1 = m;                                                \
            pS1 += step1; pM1 += step1;                                        \
        }                                                                      \
        if (isX) {                                                             \
            xsh[(P) ^ 1][tid] = xn;                                            \
            if ((TCUR) + 2 < T_STEPS) { xn = *xp; xp += stepx; }               \
        }                                                                      \
        __syncthreads();                                                       \
        if (isL2) {                                                            \
            const float4* sv = reinterpret_cast<const float4*>(&s1sh[P][s2off]);\
            float acc0 = 0.0f, acc1 = 0.0f, acc2 = 0.0f, acc3 = 0.0f;          \
            _Pragma("unroll")                                                  \
            for (int q = 0; q < 10; ++q) {                                     \
                float4 s4 = sv[q];                                             \
                float4 w4 = w2v[q];                                            \
                acc0 = fmaf(s4.x, w4.x, acc0);                                 \
                acc1 = fmaf(s4.y, w4.y, acc1);                                 \
                acc2 = fmaf(s4.z, w4.z, acc2);                                 \
                acc3 = fmaf(s4.w, w4.w, acc3);                                 \
            }                                                                  \
            float cur2 = (acc0 + acc1) + (acc2 + acc3);                        \
            float m = fmaf(beta2, mem2, cur2);                                 \
            float s = (m > thr) ? 1.0f : 0.0f;                                 \
            m = fmaf(-s, thr, m);                                              \
            mem2 = m;                                                          \
            *pS2 = s; *pM2 = m;                                                \
            pS2 += step2; pM2 += step2;                                        \
        }                                                                      \
    }

    #pragma unroll 1
    for (int t = 0; t < T_STEPS; t += 2) {
        SNN_STEP(0, t)
        SNN_STEP(1, t + 1)
    }
#undef SNN_STEP
}

extern "C" void kernel_launch(void* const* d_in, const int* in_sizes, int n_in,
                              void* d_out, int out_size)
{
    const float* x   = (const float*)d_in[0];
    const float* W1  = (const float*)d_in[1];
    const float* V   = (const float*)d_in[2];
    const float* W2  = (const float*)d_in[3];
    const float* b1  = (const float*)d_in[4];
    const float* b2  = (const float*)d_in[5];
    const float* th  = (const float*)d_in[6];
    float* out = (float*)d_out;

    dim3 grid(BATCH / NB);   // 512 blocks; 4 blocks/SM resident -> single wave
    dim3 block(NTHREADS);
    snn_scan_kernel<<<grid, block>>>(x, W1, V, W2, b1, b2, th, out);
}